// round 3
// baseline (speedup 1.0000x reference)
#include <cuda_runtime.h>
#include <cstddef>

#define BB 2
#define SS 2048
#define DD 1024
#define HH 16
#define DHH 64
#define WINDOW 256

// Scratch (allocation-free rule: __device__ globals)
__device__ float g_q[BB * SS * DD];
__device__ float g_k[BB * SS * DD];
__device__ float g_v[BB * SS * DD];
__device__ float g_attn[BB * SS * DD];

// ---------------------------------------------------------------------------
// C[M,N] = A[M,K] @ W[N,K]^T + bias[N]   (fp32, 128x128x8 tile, 8x8/thread)
// ---------------------------------------------------------------------------
__global__ __launch_bounds__(256, 2)
void gemm_bias_kernel(const float* __restrict__ A, const float* __restrict__ W,
                      const float* __restrict__ bias, float* __restrict__ C,
                      int M, int N, int K)
{
    __shared__ float As[8][128];
    __shared__ float Ws[8][128];

    const int tid = threadIdx.x;
    const int ty = tid >> 4;        // 0..15
    const int tx = tid & 15;        // 0..15
    const int m0 = blockIdx.y * 128;
    const int n0 = blockIdx.x * 128;

    const int lr = tid >> 1;        // 0..127 load row
    const int lc = (tid & 1) << 2;  // 0 or 4

    const float* Ag = A + (size_t)(m0 + lr) * K + lc;
    const float* Wg = W + (size_t)(n0 + lr) * K + lc;

    float acc[8][8];
#pragma unroll
    for (int i = 0; i < 8; i++)
#pragma unroll
        for (int j = 0; j < 8; j++) acc[i][j] = 0.f;

    for (int k0 = 0; k0 < K; k0 += 8) {
        float4 av = *(const float4*)(Ag + k0);
        float4 wv = *(const float4*)(Wg + k0);
        __syncthreads();
        As[lc + 0][lr] = av.x; As[lc + 1][lr] = av.y;
        As[lc + 2][lr] = av.z; As[lc + 3][lr] = av.w;
        Ws[lc + 0][lr] = wv.x; Ws[lc + 1][lr] = wv.y;
        Ws[lc + 2][lr] = wv.z; Ws[lc + 3][lr] = wv.w;
        __syncthreads();
#pragma unroll
        for (int kk = 0; kk < 8; kk++) {
            float4 a0 = *(float4*)(&As[kk][ty * 4]);
            float4 a1 = *(float4*)(&As[kk][64 + ty * 4]);
            float4 b0 = *(float4*)(&Ws[kk][tx * 4]);
            float4 b1 = *(float4*)(&Ws[kk][64 + tx * 4]);
            float ar[8] = {a0.x, a0.y, a0.z, a0.w, a1.x, a1.y, a1.z, a1.w};
            float br[8] = {b0.x, b0.y, b0.z, b0.w, b1.x, b1.y, b1.z, b1.w};
#pragma unroll
            for (int i = 0; i < 8; i++)
#pragma unroll
                for (int j = 0; j < 8; j++)
                    acc[i][j] += ar[i] * br[j];
        }
    }

    float4 bb0 = *(const float4*)(bias + n0 + tx * 4);
    float4 bb1 = *(const float4*)(bias + n0 + 64 + tx * 4);
    const float bbr[8] = {bb0.x, bb0.y, bb0.z, bb0.w, bb1.x, bb1.y, bb1.z, bb1.w};

#pragma unroll
    for (int i = 0; i < 8; i++) {
        int r = m0 + ((i < 4) ? (ty * 4 + i) : (64 + ty * 4 + (i - 4)));
        float4 o0 = make_float4(acc[i][0] + bbr[0], acc[i][1] + bbr[1],
                                acc[i][2] + bbr[2], acc[i][3] + bbr[3]);
        float4 o1 = make_float4(acc[i][4] + bbr[4], acc[i][5] + bbr[5],
                                acc[i][6] + bbr[6], acc[i][7] + bbr[7]);
        *(float4*)(C + (size_t)r * N + n0 + tx * 4) = o0;
        *(float4*)(C + (size_t)r * N + n0 + 64 + tx * 4) = o1;
    }
}

// ---------------------------------------------------------------------------
// Windowed causal attention, flash-style online softmax.
// Block: 256 threads, 64 queries of one (b,h). Key blocks of 32.
//   Q tile:  smem [64][64]          (reads are broadcast -> no pad)
//   K tile:  smem [32][68] padded   (conflict-free LDS.128), reused as P[64][32]
//   V tile:  smem [32][64]
// Thread (ty,tx) 16x16: owns score rows 4ty..4ty+3; score cols {tx, tx+16};
// output cols 4tx..4tx+3 (float4 store).
// ---------------------------------------------------------------------------
__global__ __launch_bounds__(256)
void attn_window_kernel()
{
    __shared__ float Qs[64 * 64];
    __shared__ float KPs[32 * 68];   // K tile (rows of 68) / reused as P (64*32)
    __shared__ float Vs[32 * 64];

    const int qt = blockIdx.x;            // 0..31 query tile
    const int bh = blockIdx.y;            // 0..31
    const int b = bh >> 4;
    const int h = bh & 15;
    const int q0 = qt * 64;

    const int tid = threadIdx.x;
    const int ty = tid >> 4;
    const int tx = tid & 15;

    const float* qbase = g_q + (size_t)(b * SS) * DD + h * DHH;
    const float* kbase = g_k + (size_t)(b * SS) * DD + h * DHH;
    const float* vbase = g_v + (size_t)(b * SS) * DD + h * DHH;

    // Load Q tile (64 rows x 64 floats) as float4
#pragma unroll
    for (int it = 0; it < 4; it++) {
        int idx = tid + it * 256;         // float4 index 0..1023
        int r = idx >> 4;
        int d4g = idx & 15;
        float4 v = *(const float4*)(qbase + (size_t)(q0 + r) * DD + (d4g << 2));
        ((float4*)Qs)[r * 16 + d4g] = v;
    }

    float m_i[4], l_i[4], acc[4][4];
#pragma unroll
    for (int i = 0; i < 4; i++) {
        m_i[i] = -1e30f;
        l_i[i] = 0.f;
#pragma unroll
        for (int j = 0; j < 4; j++) acc[i][j] = 0.f;
    }

    const float scale = 0.125f;  // 1/sqrt(64)

    for (int kb = 0; kb < 10; kb++) {
        int kstart = q0 - 256 + kb * 32;
        if (kstart < 0) continue;         // uniform across block

        __syncthreads();                  // prior P/V reads + Q stores done
        // Load K (padded 68/row) and V tiles: 32 rows x 64 floats each
#pragma unroll
        for (int it = 0; it < 2; it++) {
            int idx = tid + it * 256;     // float4 index 0..511
            int c = idx >> 4;
            int d4g = idx & 15;
            size_t row = (size_t)(kstart + c) * DD + (d4g << 2);
            float4 kv = *(const float4*)(kbase + row);
            ((float4*)KPs)[c * 17 + d4g] = kv;
            float4 vv = *(const float4*)(vbase + row);
            ((float4*)Vs)[c * 16 + d4g] = vv;
        }
        __syncthreads();

        // S = Q @ K^T (raw dot), rows 4ty+i, cols {tx, tx+16}
        float sv[4][2] = {{0.f, 0.f}, {0.f, 0.f}, {0.f, 0.f}, {0.f, 0.f}};
#pragma unroll
        for (int d4g = 0; d4g < 16; d4g++) {
            float4 kv0 = ((float4*)KPs)[tx * 17 + d4g];
            float4 kv1 = ((float4*)KPs)[(tx + 16) * 17 + d4g];
#pragma unroll
            for (int i = 0; i < 4; i++) {
                float4 qv = ((float4*)Qs)[(4 * ty + i) * 16 + d4g];
                sv[i][0] += qv.x * kv0.x + qv.y * kv0.y + qv.z * kv0.z + qv.w * kv0.w;
                sv[i][1] += qv.x * kv1.x + qv.y * kv1.y + qv.z * kv1.z + qv.w * kv1.w;
            }
        }
        __syncthreads();                  // all K reads done before P overwrites KPs

        // Online softmax update + write P
        const int k0g = kstart + tx;
        const int k1g = kstart + tx + 16;
#pragma unroll
        for (int i = 0; i < 4; i++) {
            int qglob = q0 + 4 * ty + i;
            bool v0 = (k0g <= qglob) && (qglob - k0g < WINDOW);
            bool v1 = (k1g <= qglob) && (qglob - k1g < WINDOW);
            float s0 = v0 ? sv[i][0] * scale : -1e30f;
            float s1 = v1 ? sv[i][1] * scale : -1e30f;
            float mloc = fmaxf(s0, s1);
#pragma unroll
            for (int off = 1; off < 16; off <<= 1)
                mloc = fmaxf(mloc, __shfl_xor_sync(0xffffffffu, mloc, off));
            float mnew = fmaxf(m_i[i], mloc);
            float fac = __expf(m_i[i] - mnew);   // -1e30 cases: exp(0)=1 with acc=l=0
            float p0 = v0 ? __expf(s0 - mnew) : 0.f;
            float p1 = v1 ? __expf(s1 - mnew) : 0.f;
            float ps = p0 + p1;
#pragma unroll
            for (int off = 1; off < 16; off <<= 1)
                ps += __shfl_xor_sync(0xffffffffu, ps, off);
            l_i[i] = l_i[i] * fac + ps;
            m_i[i] = mnew;
            acc[i][0] *= fac; acc[i][1] *= fac; acc[i][2] *= fac; acc[i][3] *= fac;
            KPs[(4 * ty + i) * 32 + tx] = p0;
            KPs[(4 * ty + i) * 32 + tx + 16] = p1;
        }
        __syncthreads();

        // acc += P @ V   (output cols 4tx..4tx+3)
#pragma unroll
        for (int c = 0; c < 32; c++) {
            float4 vv = ((float4*)Vs)[c * 16 + tx];
#pragma unroll
            for (int i = 0; i < 4; i++) {
                float pv = KPs[(4 * ty + i) * 32 + c];
                acc[i][0] += pv * vv.x;
                acc[i][1] += pv * vv.y;
                acc[i][2] += pv * vv.z;
                acc[i][3] += pv * vv.w;
            }
        }
    }

    float* obase = g_attn + (size_t)(b * SS) * DD + h * DHH;
#pragma unroll
    for (int i = 0; i < 4; i++) {
        float inv = 1.f / l_i[i];
        float4 o = make_float4(acc[i][0] * inv, acc[i][1] * inv,
                               acc[i][2] * inv, acc[i][3] * inv);
        *(float4*)(obase + (size_t)(q0 + 4 * ty + i) * DD + 4 * tx) = o;
    }
}

// ---------------------------------------------------------------------------
extern "C" void kernel_launch(void* const* d_in, const int* in_sizes, int n_in,
                              void* d_out, int out_size)
{
    (void)in_sizes; (void)n_in; (void)out_size;
    const float* query = (const float*)d_in[0];
    const float* key   = (const float*)d_in[1];
    const float* value = (const float*)d_in[2];
    const float* Wq = (const float*)d_in[3];
    const float* bq = (const float*)d_in[4];
    const float* Wk = (const float*)d_in[5];
    const float* bk = (const float*)d_in[6];
    const float* Wv = (const float*)d_in[7];
    const float* bv = (const float*)d_in[8];
    const float* Wo = (const float*)d_in[9];
    const float* bo = (const float*)d_in[10];
    float* out = (float*)d_out;

    float *qp, *kp, *vp, *ap;
    cudaGetSymbolAddress((void**)&qp, g_q);
    cudaGetSymbolAddress((void**)&kp, g_k);
    cudaGetSymbolAddress((void**)&vp, g_v);
    cudaGetSymbolAddress((void**)&ap, g_attn);

    const int M = BB * SS;  // 4096
    dim3 blk(256);
    dim3 grd(DD / 128, M / 128);  // (8, 32)

    gemm_bias_kernel<<<grd, blk>>>(query, Wq, bq, qp, M, DD, DD);
    gemm_bias_kernel<<<grd, blk>>>(key,   Wk, bk, kp, M, DD, DD);
    gemm_bias_kernel<<<grd, blk>>>(value, Wv, bv, vp, M, DD, DD);

    attn_window_kernel<<<dim3(SS / 64, BB * HH), blk>>>();

    gemm_bias_kernel<<<grd, blk>>>(ap, Wo, bo, out, M, DD, DD);
}

// round 8
// speedup vs baseline: 1.7237x; 1.7237x over previous
#include <cuda_runtime.h>
#include <cuda_bf16.h>
#include <cstdint>
#include <cstddef>

#define BB 2
#define SS 2048
#define DD 1024
#define HH 16
#define DHH 64
#define WINDOW 256
#define MM (BB * SS)        // 4096 activation rows
#define K3 3072             // 3-way split K
#define NST 96              // K3 / 32 pipeline stages

// ---------------- scratch (__device__ globals; no allocs allowed) ----------
__device__ float g_q[BB * SS * DD];
__device__ float g_k[BB * SS * DD];
__device__ float g_v[BB * SS * DD];
__device__ float g_attn[BB * SS * DD];
__device__ __nv_bfloat16 g_a2[(size_t)MM * K3];   // split activations
__device__ __nv_bfloat16 g_w2[(size_t)DD * K3];   // split weights

// ---------------- PTX helpers (plain sm_103-safe subset) -------------------
__device__ __forceinline__ uint32_t smem_u32(const void* p) {
    uint32_t a;
    asm("{ .reg .u64 t; cvta.to.shared.u64 t, %1; cvt.u32.u64 %0, t; }"
        : "=r"(a) : "l"(p));
    return a;
}
__device__ __forceinline__ void cp_async16(uint32_t saddr, const void* gaddr) {
    asm volatile("cp.async.cg.shared.global [%0], [%1], 16;"
                 :: "r"(saddr), "l"(gaddr));
}
#define CP_COMMIT() asm volatile("cp.async.commit_group;" ::: "memory")
#define CP_WAIT2()  asm volatile("cp.async.wait_group 2;" ::: "memory")

__device__ __forceinline__ void ldmatrix_x4(uint32_t* r, uint32_t addr) {
    asm volatile("ldmatrix.sync.aligned.m8n8.x4.shared.b16 {%0,%1,%2,%3}, [%4];"
                 : "=r"(r[0]), "=r"(r[1]), "=r"(r[2]), "=r"(r[3]) : "r"(addr));
}
__device__ __forceinline__ void mma_bf16(float* d, const uint32_t* a,
                                         uint32_t b0, uint32_t b1) {
    asm volatile(
        "mma.sync.aligned.m16n8k16.row.col.f32.bf16.bf16.f32 "
        "{%0,%1,%2,%3}, {%4,%5,%6,%7}, {%8,%9}, {%0,%1,%2,%3};"
        : "+f"(d[0]), "+f"(d[1]), "+f"(d[2]), "+f"(d[3])
        : "r"(a[0]), "r"(a[1]), "r"(a[2]), "r"(a[3]), "r"(b0), "r"(b1));
}

// ---------------------------------------------------------------------------
// fp32 -> bf16 3-way split. AMODE=1: [hi|lo|hi] (activations)
//                           AMODE=0: [hi|hi|lo] (weights)
// ---------------------------------------------------------------------------
template <int AMODE>
__global__ void split_kernel(const float* __restrict__ in,
                             __nv_bfloat16* __restrict__ out, int rows)
{
    int i4 = blockIdx.x * blockDim.x + threadIdx.x;
    if (i4 >= rows * (DD / 4)) return;
    int row = i4 >> 8;          // DD/4 = 256
    int c4 = i4 & 255;
    float4 f = ((const float4*)in)[i4];

    __nv_bfloat16 h0 = __float2bfloat16(f.x);
    __nv_bfloat16 h1 = __float2bfloat16(f.y);
    __nv_bfloat16 h2 = __float2bfloat16(f.z);
    __nv_bfloat16 h3 = __float2bfloat16(f.w);
    __nv_bfloat16 l0 = __float2bfloat16(f.x - __bfloat162float(h0));
    __nv_bfloat16 l1 = __float2bfloat16(f.y - __bfloat162float(h1));
    __nv_bfloat16 l2 = __float2bfloat16(f.z - __bfloat162float(h2));
    __nv_bfloat16 l3 = __float2bfloat16(f.w - __bfloat162float(h3));

    __nv_bfloat162 hA, hB, lA, lB;
    hA.x = h0; hA.y = h1; hB.x = h2; hB.y = h3;
    lA.x = l0; lA.y = l1; lB.x = l2; lB.y = l3;

    size_t base = (size_t)row * K3 + c4 * 4;
    __nv_bfloat162* o0 = (__nv_bfloat162*)(out + base);
    __nv_bfloat162* o1 = (__nv_bfloat162*)(out + base + 1024);
    __nv_bfloat162* o2 = (__nv_bfloat162*)(out + base + 2048);
    o0[0] = hA; o0[1] = hB;
    if (AMODE) { o1[0] = lA; o1[1] = lB; o2[0] = hA; o2[1] = hB; }
    else       { o1[0] = hA; o1[1] = hB; o2[0] = lA; o2[1] = lB; }
}

// ---------------------------------------------------------------------------
// mma.sync bf16 GEMM: C[MM,DD] = A2[MM,K3] @ W2[DD,K3]^T + bias
// CTA 128x128, 8 warps (2 M x 4 N), warp tile 64x32.
// 4-stage cp.async pipeline, 32 K-elems (2x k16) per stage.
// smem tile layout: [row][32 bf16] (64B rows), 16B chunk swizzle c^((row>>1)&3)
//   -> conflict-free for cp.async stores and all ldmatrix phases.
// ---------------------------------------------------------------------------
__global__ __launch_bounds__(256, 2)
void gemm_mma_kernel(const __nv_bfloat16* __restrict__ A2,
                     const __nv_bfloat16* __restrict__ W2,
                     const float* __restrict__ bias,
                     float* __restrict__ C)
{
    extern __shared__ char smem_raw[];            // 4 stages x (A 8KB | B 8KB)
    const uint32_t smem = smem_u32(smem_raw);

    const int tid  = threadIdx.x;
    const int wid  = tid >> 5;
    const int lane = tid & 31;
    const int wm = wid & 1;                       // M warp group (0..1)
    const int wn = wid >> 1;                      // N warp group (0..3)
    const int n0 = blockIdx.x * 128;
    const int m0 = blockIdx.y * 128;

    const __nv_bfloat16* Abase = A2 + (size_t)m0 * K3;
    const __nv_bfloat16* Wbase = W2 + (size_t)n0 * K3;

    // per-thread cp.async source/dest components (2 chunks each for A and B)
    const int cl0 = tid;                          // chunk-linear ids
    const int cl1 = tid + 256;
    const int lr0 = cl0 >> 2, lc0 = cl0 & 3;
    const int lr1 = cl1 >> 2, lc1 = cl1 & 3;
    const uint32_t so0 = lr0 * 64 + ((lc0 ^ ((lr0 >> 1) & 3)) << 4);
    const uint32_t so1 = lr1 * 64 + ((lc1 ^ ((lr1 >> 1) & 3)) << 4);

    // per-thread ldmatrix address components
    const int lane15 = lane & 15;
    const int hib = lane >> 4;                    // 0/1: k-chunk parity bit
    uint32_t a_off[4], b_off[2];
    int a_sw[4], b_sw[2];
#pragma unroll
    for (int mt = 0; mt < 4; mt++) {
        int r = wm * 64 + mt * 16 + lane15;
        a_off[mt] = r * 64;
        a_sw[mt] = (r >> 1) & 3;
    }
#pragma unroll
    for (int bp = 0; bp < 2; bp++) {
        int r = wn * 32 + bp * 16 + lane15;
        b_off[bp] = 8192 + r * 64;
        b_sw[bp] = (r >> 1) & 3;
    }

    float d[4][4][4];
#pragma unroll
    for (int mt = 0; mt < 4; mt++)
#pragma unroll
        for (int nt = 0; nt < 4; nt++)
#pragma unroll
            for (int j = 0; j < 4; j++) d[mt][nt][j] = 0.f;

    // ---- pipeline prologue: stages 0..2
#pragma unroll
    for (int st = 0; st < 3; st++) {
        uint32_t sb = smem + (st & 3) * 16384;
        const __nv_bfloat16* Ag = Abase + st * 32;
        const __nv_bfloat16* Wg = Wbase + st * 32;
        cp_async16(sb + so0,        Ag + (size_t)lr0 * K3 + lc0 * 8);
        cp_async16(sb + 8192 + so0, Wg + (size_t)lr0 * K3 + lc0 * 8);
        cp_async16(sb + so1,        Ag + (size_t)lr1 * K3 + lc1 * 8);
        cp_async16(sb + 8192 + so1, Wg + (size_t)lr1 * K3 + lc1 * 8);
        CP_COMMIT();
    }

    // ---- main loop
    for (int st = 0; st < NST; st++) {
        CP_WAIT2();
        __syncthreads();

        // prefetch stage st+3 (empty commit keeps wait_group arithmetic valid)
        int pf = st + 3;
        if (pf < NST) {
            uint32_t sb = smem + (pf & 3) * 16384;
            const __nv_bfloat16* Ag = Abase + pf * 32;
            const __nv_bfloat16* Wg = Wbase + pf * 32;
            cp_async16(sb + so0,        Ag + (size_t)lr0 * K3 + lc0 * 8);
            cp_async16(sb + 8192 + so0, Wg + (size_t)lr0 * K3 + lc0 * 8);
            cp_async16(sb + so1,        Ag + (size_t)lr1 * K3 + lc1 * 8);
            cp_async16(sb + 8192 + so1, Wg + (size_t)lr1 * K3 + lc1 * 8);
        }
        CP_COMMIT();

        // compute 2 x k16 on stage st
        uint32_t base = smem + (st & 3) * 16384;
#pragma unroll
        for (int s16 = 0; s16 < 2; s16++) {
            int ch = s16 * 2 + hib;
            uint32_t a[4][4], bb[2][4];
#pragma unroll
            for (int mt = 0; mt < 4; mt++)
                ldmatrix_x4(a[mt], base + a_off[mt] + ((ch ^ a_sw[mt]) << 4));
#pragma unroll
            for (int bp = 0; bp < 2; bp++)
                ldmatrix_x4(bb[bp], base + b_off[bp] + ((ch ^ b_sw[bp]) << 4));
            // B regs from ldmatrix: r0=(n0-7,k0-7) r1=(n8-15,k0-7)
            //                       r2=(n0-7,k8-15) r3=(n8-15,k8-15)
            // mma needs (b0=k0-7, b1=k8-15) at same n-block:
            //   nt&1 selects n-8-block, +2 selects k-hi half.
#pragma unroll
            for (int mt = 0; mt < 4; mt++)
#pragma unroll
                for (int nt = 0; nt < 4; nt++)
                    mma_bf16(d[mt][nt], a[mt],
                             bb[nt >> 1][nt & 1],
                             bb[nt >> 1][(nt & 1) + 2]);
        }
    }

    // ---- epilogue: bias add + fp32 store
    const int ncol0 = n0 + wn * 32 + (lane & 3) * 2;
    const int mrow0 = m0 + wm * 64 + (lane >> 2);
#pragma unroll
    for (int nt = 0; nt < 4; nt++) {
        float2 bv = *(const float2*)(bias + ncol0 + nt * 8);
#pragma unroll
        for (int mt = 0; mt < 4; mt++) {
            int r1 = mrow0 + mt * 16;
            float2 o0 = make_float2(d[mt][nt][0] + bv.x, d[mt][nt][1] + bv.y);
            float2 o1 = make_float2(d[mt][nt][2] + bv.x, d[mt][nt][3] + bv.y);
            *(float2*)(C + (size_t)r1 * DD + ncol0 + nt * 8) = o0;
            *(float2*)(C + (size_t)(r1 + 8) * DD + ncol0 + nt * 8) = o1;
        }
    }
}

// ---------------------------------------------------------------------------
// Windowed causal attention (unchanged from passing R2 kernel, 186us)
// ---------------------------------------------------------------------------
__global__ __launch_bounds__(256)
void attn_window_kernel()
{
    __shared__ float Qs[64 * 64];
    __shared__ float KPs[32 * 68];
    __shared__ float Vs[32 * 64];

    const int qt = blockIdx.x;
    const int bh = blockIdx.y;
    const int b = bh >> 4;
    const int h = bh & 15;
    const int q0 = qt * 64;

    const int tid = threadIdx.x;
    const int ty = tid >> 4;
    const int tx = tid & 15;

    const float* qbase = g_q + (size_t)(b * SS) * DD + h * DHH;
    const float* kbase = g_k + (size_t)(b * SS) * DD + h * DHH;
    const float* vbase = g_v + (size_t)(b * SS) * DD + h * DHH;

#pragma unroll
    for (int it = 0; it < 4; it++) {
        int idx = tid + it * 256;
        int r = idx >> 4;
        int d4g = idx & 15;
        float4 v = *(const float4*)(qbase + (size_t)(q0 + r) * DD + (d4g << 2));
        ((float4*)Qs)[r * 16 + d4g] = v;
    }

    float m_i[4], l_i[4], acc[4][4];
#pragma unroll
    for (int i = 0; i < 4; i++) {
        m_i[i] = -1e30f;
        l_i[i] = 0.f;
#pragma unroll
        for (int j = 0; j < 4; j++) acc[i][j] = 0.f;
    }

    const float scale = 0.125f;

    for (int kb = 0; kb < 10; kb++) {
        int kstart = q0 - 256 + kb * 32;
        if (kstart < 0) continue;

        __syncthreads();
#pragma unroll
        for (int it = 0; it < 2; it++) {
            int idx = tid + it * 256;
            int c = idx >> 4;
            int d4g = idx & 15;
            size_t row = (size_t)(kstart + c) * DD + (d4g << 2);
            float4 kv = *(const float4*)(kbase + row);
            ((float4*)KPs)[c * 17 + d4g] = kv;
            float4 vv = *(const float4*)(vbase + row);
            ((float4*)Vs)[c * 16 + d4g] = vv;
        }
        __syncthreads();

        float sv[4][2] = {{0.f, 0.f}, {0.f, 0.f}, {0.f, 0.f}, {0.f, 0.f}};
#pragma unroll
        for (int d4g = 0; d4g < 16; d4g++) {
            float4 kv0 = ((float4*)KPs)[tx * 17 + d4g];
            float4 kv1 = ((float4*)KPs)[(tx + 16) * 17 + d4g];
#pragma unroll
            for (int i = 0; i < 4; i++) {
                float4 qv = ((float4*)Qs)[(4 * ty + i) * 16 + d4g];
                sv[i][0] += qv.x * kv0.x + qv.y * kv0.y + qv.z * kv0.z + qv.w * kv0.w;
                sv[i][1] += qv.x * kv1.x + qv.y * kv1.y + qv.z * kv1.z + qv.w * kv1.w;
            }
        }
        __syncthreads();

        const int k0g = kstart + tx;
        const int k1g = kstart + tx + 16;
#pragma unroll
        for (int i = 0; i < 4; i++) {
            int qglob = q0 + 4 * ty + i;
            bool v0 = (k0g <= qglob) && (qglob - k0g < WINDOW);
            bool v1 = (k1g <= qglob) && (qglob - k1g < WINDOW);
            float s0 = v0 ? sv[i][0] * scale : -1e30f;
            float s1 = v1 ? sv[i][1] * scale : -1e30f;
            float mloc = fmaxf(s0, s1);
#pragma unroll
            for (int off = 1; off < 16; off <<= 1)
                mloc = fmaxf(mloc, __shfl_xor_sync(0xffffffffu, mloc, off));
            float mnew = fmaxf(m_i[i], mloc);
            float fac = __expf(m_i[i] - mnew);
            float p0 = v0 ? __expf(s0 - mnew) : 0.f;
            float p1 = v1 ? __expf(s1 - mnew) : 0.f;
            float ps = p0 + p1;
#pragma unroll
            for (int off = 1; off < 16; off <<= 1)
                ps += __shfl_xor_sync(0xffffffffu, ps, off);
            l_i[i] = l_i[i] * fac + ps;
            m_i[i] = mnew;
            acc[i][0] *= fac; acc[i][1] *= fac; acc[i][2] *= fac; acc[i][3] *= fac;
            KPs[(4 * ty + i) * 32 + tx] = p0;
            KPs[(4 * ty + i) * 32 + tx + 16] = p1;
        }
        __syncthreads();

#pragma unroll
        for (int c = 0; c < 32; c++) {
            float4 vv = ((float4*)Vs)[c * 16 + tx];
#pragma unroll
            for (int i = 0; i < 4; i++) {
                float pv = KPs[(4 * ty + i) * 32 + c];
                acc[i][0] += pv * vv.x;
                acc[i][1] += pv * vv.y;
                acc[i][2] += pv * vv.z;
                acc[i][3] += pv * vv.w;
            }
        }
    }

    float* obase = g_attn + (size_t)(b * SS) * DD + h * DHH;
#pragma unroll
    for (int i = 0; i < 4; i++) {
        float inv = 1.f / l_i[i];
        float4 o = make_float4(acc[i][0] * inv, acc[i][1] * inv,
                               acc[i][2] * inv, acc[i][3] * inv);
        *(float4*)(obase + (size_t)(q0 + 4 * ty + i) * DD + 4 * tx) = o;
    }
}

// ---------------------------------------------------------------------------
extern "C" void kernel_launch(void* const* d_in, const int* in_sizes, int n_in,
                              void* d_out, int out_size)
{
    (void)in_sizes; (void)n_in; (void)out_size;
    const float* query = (const float*)d_in[0];
    const float* key   = (const float*)d_in[1];
    const float* value = (const float*)d_in[2];
    const float* Wq = (const float*)d_in[3];
    const float* bq = (const float*)d_in[4];
    const float* Wk = (const float*)d_in[5];
    const float* bk = (const float*)d_in[6];
    const float* Wv = (const float*)d_in[7];
    const float* bv = (const float*)d_in[8];
    const float* Wo = (const float*)d_in[9];
    const float* bo = (const float*)d_in[10];
    float* out = (float*)d_out;

    float *qp, *kp, *vp, *ap;
    __nv_bfloat16 *a2, *w2;
    cudaGetSymbolAddress((void**)&qp, g_q);
    cudaGetSymbolAddress((void**)&kp, g_k);
    cudaGetSymbolAddress((void**)&vp, g_v);
    cudaGetSymbolAddress((void**)&ap, g_attn);
    cudaGetSymbolAddress((void**)&a2, g_a2);
    cudaGetSymbolAddress((void**)&w2, g_w2);

    const int SMEM_GEMM = 4 * 16384;   // 4 stages x (A 8KB + B 8KB)
    cudaFuncSetAttribute(gemm_mma_kernel,
                         cudaFuncAttributeMaxDynamicSharedMemorySize, SMEM_GEMM);

    dim3 gblk(256);
    dim3 ggrd(DD / 128, MM / 128);     // (8, 32)
    const int SPA_GRID = MM;
    const int SPW_GRID = DD;

    // Q = query @ Wq^T + bq
    split_kernel<1><<<SPA_GRID, 256>>>(query, a2, MM);
    split_kernel<0><<<SPW_GRID, 256>>>(Wq, w2, DD);
    gemm_mma_kernel<<<ggrd, gblk, SMEM_GEMM>>>(a2, w2, bq, qp);
    // K
    split_kernel<1><<<SPA_GRID, 256>>>(key, a2, MM);
    split_kernel<0><<<SPW_GRID, 256>>>(Wk, w2, DD);
    gemm_mma_kernel<<<ggrd, gblk, SMEM_GEMM>>>(a2, w2, bk, kp);
    // V
    split_kernel<1><<<SPA_GRID, 256>>>(value, a2, MM);
    split_kernel<0><<<SPW_GRID, 256>>>(Wv, w2, DD);
    gemm_mma_kernel<<<ggrd, gblk, SMEM_GEMM>>>(a2, w2, bv, vp);

    attn_window_kernel<<<dim3(SS / 64, BB * HH), gblk>>>();

    // out = attn @ Wo^T + bo
    split_kernel<1><<<SPA_GRID, 256>>>(ap, a2, MM);
    split_kernel<0><<<SPW_GRID, 256>>>(Wo, w2, DD);
    gemm_mma_kernel<<<ggrd, gblk, SMEM_GEMM>>>(a2, w2, bo, out);
}

// round 10
// speedup vs baseline: 1.8081x; 1.0490x over previous
#include <cuda_runtime.h>
#include <cuda_bf16.h>
#include <cstdint>
#include <cstddef>

#define BB 2
#define SS 2048
#define DD 1024
#define HH 16
#define DHH 64
#define WINDOW 256
#define MM (BB * SS)        // 4096 activation rows
#define K3 3072             // 3-way split K
#define NST 96              // K3 / 32 pipeline stages

// ---------------- scratch (__device__ globals; no allocs allowed) ----------
__device__ float g_q[BB * SS * DD];
__device__ float g_k[BB * SS * DD];
__device__ float g_v[BB * SS * DD];
__device__ __nv_bfloat16 g_a2[(size_t)MM * K3];   // split activations
__device__ __nv_bfloat16 g_w2[(size_t)DD * K3];   // split weights

// ---------------- PTX helpers (plain sm_103-safe subset) -------------------
__device__ __forceinline__ uint32_t smem_u32(const void* p) {
    uint32_t a;
    asm("{ .reg .u64 t; cvta.to.shared.u64 t, %1; cvt.u32.u64 %0, t; }"
        : "=r"(a) : "l"(p));
    return a;
}
__device__ __forceinline__ void cp_async16(uint32_t saddr, const void* gaddr) {
    asm volatile("cp.async.cg.shared.global [%0], [%1], 16;"
                 :: "r"(saddr), "l"(gaddr));
}
#define CP_COMMIT() asm volatile("cp.async.commit_group;" ::: "memory")
#define CP_WAIT2()  asm volatile("cp.async.wait_group 2;" ::: "memory")

__device__ __forceinline__ void ldmatrix_x4(uint32_t* r, uint32_t addr) {
    asm volatile("ldmatrix.sync.aligned.m8n8.x4.shared.b16 {%0,%1,%2,%3}, [%4];"
                 : "=r"(r[0]), "=r"(r[1]), "=r"(r[2]), "=r"(r[3]) : "r"(addr));
}
__device__ __forceinline__ void mma_bf16(float* d, const uint32_t* a,
                                         uint32_t b0, uint32_t b1) {
    asm volatile(
        "mma.sync.aligned.m16n8k16.row.col.f32.bf16.bf16.f32 "
        "{%0,%1,%2,%3}, {%4,%5,%6,%7}, {%8,%9}, {%0,%1,%2,%3};"
        : "+f"(d[0]), "+f"(d[1]), "+f"(d[2]), "+f"(d[3])
        : "r"(a[0]), "r"(a[1]), "r"(a[2]), "r"(a[3]), "r"(b0), "r"(b1));
}

__device__ __forceinline__ uint32_t pack_bf16x2(float a, float b) {
    __nv_bfloat162 t;
    t.x = __float2bfloat16(a);
    t.y = __float2bfloat16(b);
    return *(uint32_t*)&t;
}

// ---------------------------------------------------------------------------
// fp32 -> bf16 3-way split. AMODE=1: [hi|lo|hi] (activations)
//                           AMODE=0: [hi|hi|lo] (weights)
// ---------------------------------------------------------------------------
template <int AMODE>
__global__ void split_kernel(const float* __restrict__ in,
                             __nv_bfloat16* __restrict__ out, int rows)
{
    int i4 = blockIdx.x * blockDim.x + threadIdx.x;
    if (i4 >= rows * (DD / 4)) return;
    int row = i4 >> 8;          // DD/4 = 256
    int c4 = i4 & 255;
    float4 f = ((const float4*)in)[i4];

    __nv_bfloat16 h0 = __float2bfloat16(f.x);
    __nv_bfloat16 h1 = __float2bfloat16(f.y);
    __nv_bfloat16 h2 = __float2bfloat16(f.z);
    __nv_bfloat16 h3 = __float2bfloat16(f.w);
    __nv_bfloat16 l0 = __float2bfloat16(f.x - __bfloat162float(h0));
    __nv_bfloat16 l1 = __float2bfloat16(f.y - __bfloat162float(h1));
    __nv_bfloat16 l2 = __float2bfloat16(f.z - __bfloat162float(h2));
    __nv_bfloat16 l3 = __float2bfloat16(f.w - __bfloat162float(h3));

    __nv_bfloat162 hA, hB, lA, lB;
    hA.x = h0; hA.y = h1; hB.x = h2; hB.y = h3;
    lA.x = l0; lA.y = l1; lB.x = l2; lB.y = l3;

    size_t base = (size_t)row * K3 + c4 * 4;
    __nv_bfloat162* o0 = (__nv_bfloat162*)(out + base);
    __nv_bfloat162* o1 = (__nv_bfloat162*)(out + base + 1024);
    __nv_bfloat162* o2 = (__nv_bfloat162*)(out + base + 2048);
    o0[0] = hA; o0[1] = hB;
    if (AMODE) { o1[0] = lA; o1[1] = lB; o2[0] = hA; o2[1] = hB; }
    else       { o1[0] = hA; o1[1] = hB; o2[0] = lA; o2[1] = lB; }
}

// ---------------------------------------------------------------------------
// mma.sync bf16 GEMM: C[MM,DD] = A2[MM,K3] @ W2[DD,K3]^T + bias
// (unchanged from R8 — measured at legacy-HMMA ceiling ~290 TF/s)
// ---------------------------------------------------------------------------
__global__ __launch_bounds__(256, 2)
void gemm_mma_kernel(const __nv_bfloat16* __restrict__ A2,
                     const __nv_bfloat16* __restrict__ W2,
                     const float* __restrict__ bias,
                     float* __restrict__ C)
{
    extern __shared__ char smem_raw[];            // 4 stages x (A 8KB | B 8KB)
    const uint32_t smem = smem_u32(smem_raw);

    const int tid  = threadIdx.x;
    const int wid  = tid >> 5;
    const int lane = tid & 31;
    const int wm = wid & 1;                       // M warp group (0..1)
    const int wn = wid >> 1;                      // N warp group (0..3)
    const int n0 = blockIdx.x * 128;
    const int m0 = blockIdx.y * 128;

    const __nv_bfloat16* Abase = A2 + (size_t)m0 * K3;
    const __nv_bfloat16* Wbase = W2 + (size_t)n0 * K3;

    const int cl0 = tid;
    const int cl1 = tid + 256;
    const int lr0 = cl0 >> 2, lc0 = cl0 & 3;
    const int lr1 = cl1 >> 2, lc1 = cl1 & 3;
    const uint32_t so0 = lr0 * 64 + ((lc0 ^ ((lr0 >> 1) & 3)) << 4);
    const uint32_t so1 = lr1 * 64 + ((lc1 ^ ((lr1 >> 1) & 3)) << 4);

    const int lane15 = lane & 15;
    const int hib = lane >> 4;
    uint32_t a_off[4], b_off[2];
    int a_sw[4], b_sw[2];
#pragma unroll
    for (int mt = 0; mt < 4; mt++) {
        int r = wm * 64 + mt * 16 + lane15;
        a_off[mt] = r * 64;
        a_sw[mt] = (r >> 1) & 3;
    }
#pragma unroll
    for (int bp = 0; bp < 2; bp++) {
        int r = wn * 32 + bp * 16 + lane15;
        b_off[bp] = 8192 + r * 64;
        b_sw[bp] = (r >> 1) & 3;
    }

    float d[4][4][4];
#pragma unroll
    for (int mt = 0; mt < 4; mt++)
#pragma unroll
        for (int nt = 0; nt < 4; nt++)
#pragma unroll
            for (int j = 0; j < 4; j++) d[mt][nt][j] = 0.f;

#pragma unroll
    for (int st = 0; st < 3; st++) {
        uint32_t sb = smem + (st & 3) * 16384;
        const __nv_bfloat16* Ag = Abase + st * 32;
        const __nv_bfloat16* Wg = Wbase + st * 32;
        cp_async16(sb + so0,        Ag + (size_t)lr0 * K3 + lc0 * 8);
        cp_async16(sb + 8192 + so0, Wg + (size_t)lr0 * K3 + lc0 * 8);
        cp_async16(sb + so1,        Ag + (size_t)lr1 * K3 + lc1 * 8);
        cp_async16(sb + 8192 + so1, Wg + (size_t)lr1 * K3 + lc1 * 8);
        CP_COMMIT();
    }

    for (int st = 0; st < NST; st++) {
        CP_WAIT2();
        __syncthreads();

        int pf = st + 3;
        if (pf < NST) {
            uint32_t sb = smem + (pf & 3) * 16384;
            const __nv_bfloat16* Ag = Abase + pf * 32;
            const __nv_bfloat16* Wg = Wbase + pf * 32;
            cp_async16(sb + so0,        Ag + (size_t)lr0 * K3 + lc0 * 8);
            cp_async16(sb + 8192 + so0, Wg + (size_t)lr0 * K3 + lc0 * 8);
            cp_async16(sb + so1,        Ag + (size_t)lr1 * K3 + lc1 * 8);
            cp_async16(sb + 8192 + so1, Wg + (size_t)lr1 * K3 + lc1 * 8);
        }
        CP_COMMIT();

        uint32_t base = smem + (st & 3) * 16384;
#pragma unroll
        for (int s16 = 0; s16 < 2; s16++) {
            int ch = s16 * 2 + hib;
            uint32_t a[4][4], bb[2][4];
#pragma unroll
            for (int mt = 0; mt < 4; mt++)
                ldmatrix_x4(a[mt], base + a_off[mt] + ((ch ^ a_sw[mt]) << 4));
#pragma unroll
            for (int bp = 0; bp < 2; bp++)
                ldmatrix_x4(bb[bp], base + b_off[bp] + ((ch ^ b_sw[bp]) << 4));
#pragma unroll
            for (int mt = 0; mt < 4; mt++)
#pragma unroll
                for (int nt = 0; nt < 4; nt++)
                    mma_bf16(d[mt][nt], a[mt],
                             bb[nt >> 1][nt & 1],
                             bb[nt >> 1][(nt & 1) + 2]);
        }
    }

    const int ncol0 = n0 + wn * 32 + (lane & 3) * 2;
    const int mrow0 = m0 + wm * 64 + (lane >> 2);
#pragma unroll
    for (int nt = 0; nt < 4; nt++) {
        float2 bv = *(const float2*)(bias + ncol0 + nt * 8);
#pragma unroll
        for (int mt = 0; mt < 4; mt++) {
            int r1 = mrow0 + mt * 16;
            float2 o0 = make_float2(d[mt][nt][0] + bv.x, d[mt][nt][1] + bv.y);
            float2 o1 = make_float2(d[mt][nt][2] + bv.x, d[mt][nt][3] + bv.y);
            *(float2*)(C + (size_t)r1 * DD + ncol0 + nt * 8) = o0;
            *(float2*)(C + (size_t)(r1 + 8) * DD + ncol0 + nt * 8) = o1;
        }
    }
}

// ---------------------------------------------------------------------------
// Windowed causal attention, 64-query x 64-key tiles (5 phases), fused
// bf16 [hi|lo|hi] split epilogue writing g_a2 directly.
// Dynamic smem: Qs 64x64 | KPs 64x68 (K tile, reused as P) | Vs 64x64
// Thread (ty,tx) 16x16: rows 4ty..4ty+3; score cols {tx,tx+16,tx+32,tx+48};
// output cols 4tx..4tx+3.
// ---------------------------------------------------------------------------
#define ATT_SMEM ((64 * 64 + 64 * 68 + 64 * 64) * 4)   // 50176 bytes

__global__ __launch_bounds__(256, 2)
void attn_window_kernel()
{
    extern __shared__ float sm[];
    float* Qs  = sm;              // 4096 floats
    float* KPs = sm + 4096;       // 4352 floats (stride 68)
    float* Vs  = sm + 8448;       // 4096 floats

    const int qt = blockIdx.x;            // 0..31 query tile
    const int bh = blockIdx.y;            // 0..31
    const int b = bh >> 4;
    const int h = bh & 15;
    const int q0 = qt * 64;

    const int tid = threadIdx.x;
    const int ty = tid >> 4;
    const int tx = tid & 15;

    const float* qbase = g_q + (size_t)(b * SS) * DD + h * DHH;
    const float* kbase = g_k + (size_t)(b * SS) * DD + h * DHH;
    const float* vbase = g_v + (size_t)(b * SS) * DD + h * DHH;

    // Load Q tile (64 rows x 64 floats)
#pragma unroll
    for (int it = 0; it < 4; it++) {
        int idx = tid + it * 256;
        int r = idx >> 4;
        int d4g = idx & 15;
        float4 v = *(const float4*)(qbase + (size_t)(q0 + r) * DD + (d4g << 2));
        ((float4*)Qs)[r * 16 + d4g] = v;
    }

    float m_i[4], l_i[4], acc[4][4];
#pragma unroll
    for (int i = 0; i < 4; i++) {
        m_i[i] = -1e30f;
        l_i[i] = 0.f;
#pragma unroll
        for (int j = 0; j < 4; j++) acc[i][j] = 0.f;
    }

    const float scale = 0.125f;  // 1/sqrt(64)

    for (int kb = 0; kb < 5; kb++) {
        int kstart = q0 - 256 + kb * 64;
        if (kstart < 0) continue;          // uniform across block

        __syncthreads();                   // prior P/V reads + Q stores done
        // Load K (stride 68) and V tiles: 64 rows x 64 floats each
#pragma unroll
        for (int it = 0; it < 4; it++) {
            int idx = tid + it * 256;      // float4 index 0..1023
            int c = idx >> 4;
            int d4g = idx & 15;
            size_t row = (size_t)(kstart + c) * DD + (d4g << 2);
            ((float4*)KPs)[c * 17 + d4g] = *(const float4*)(kbase + row);
            ((float4*)Vs)[c * 16 + d4g]  = *(const float4*)(vbase + row);
        }
        __syncthreads();

        // S = Q @ K^T, rows 4ty+i, cols tx+16j
        float sv[4][4];
#pragma unroll
        for (int i = 0; i < 4; i++)
#pragma unroll
            for (int j = 0; j < 4; j++) sv[i][j] = 0.f;

#pragma unroll
        for (int d4g = 0; d4g < 16; d4g++) {
            float4 kv[4];
#pragma unroll
            for (int j = 0; j < 4; j++)
                kv[j] = ((float4*)KPs)[(tx + 16 * j) * 17 + d4g];
#pragma unroll
            for (int i = 0; i < 4; i++) {
                float4 qv = ((float4*)Qs)[(4 * ty + i) * 16 + d4g];
#pragma unroll
                for (int j = 0; j < 4; j++)
                    sv[i][j] += qv.x * kv[j].x + qv.y * kv[j].y +
                                qv.z * kv[j].z + qv.w * kv[j].w;
            }
        }
        __syncthreads();                   // all K reads done before P overwrite

        // Online softmax + write P (stride 68 overlay on K buffer)
#pragma unroll
        for (int i = 0; i < 4; i++) {
            int qglob = q0 + 4 * ty + i;
            float s[4], p[4];
            bool valid[4];
#pragma unroll
            for (int j = 0; j < 4; j++) {
                int kg = kstart + tx + 16 * j;
                valid[j] = (kg <= qglob) && (qglob - kg < WINDOW);
                s[j] = valid[j] ? sv[i][j] * scale : -1e30f;
            }
            float mloc = fmaxf(fmaxf(s[0], s[1]), fmaxf(s[2], s[3]));
#pragma unroll
            for (int off = 1; off < 16; off <<= 1)
                mloc = fmaxf(mloc, __shfl_xor_sync(0xffffffffu, mloc, off));
            float mnew = fmaxf(m_i[i], mloc);
            float fac = __expf(m_i[i] - mnew);
            float ps = 0.f;
#pragma unroll
            for (int j = 0; j < 4; j++) {
                p[j] = valid[j] ? __expf(s[j] - mnew) : 0.f;
                ps += p[j];
            }
#pragma unroll
            for (int off = 1; off < 16; off <<= 1)
                ps += __shfl_xor_sync(0xffffffffu, ps, off);
            l_i[i] = l_i[i] * fac + ps;
            m_i[i] = mnew;
            acc[i][0] *= fac; acc[i][1] *= fac; acc[i][2] *= fac; acc[i][3] *= fac;
#pragma unroll
            for (int j = 0; j < 4; j++)
                KPs[(4 * ty + i) * 68 + tx + 16 * j] = p[j];
        }
        __syncthreads();

        // acc += P @ V   (output cols 4tx..4tx+3)
#pragma unroll
        for (int c = 0; c < 64; c++) {
            float4 vv = ((float4*)Vs)[c * 16 + tx];
#pragma unroll
            for (int i = 0; i < 4; i++) {
                float pv = KPs[(4 * ty + i) * 68 + c];
                acc[i][0] += pv * vv.x;
                acc[i][1] += pv * vv.y;
                acc[i][2] += pv * vv.z;
                acc[i][3] += pv * vv.w;
            }
        }
    }

    // ---- epilogue: normalize and write bf16 [hi|lo|hi] split into g_a2 ----
#pragma unroll
    for (int i = 0; i < 4; i++) {
        float inv = 1.f / l_i[i];
        float o0 = acc[i][0] * inv, o1 = acc[i][1] * inv;
        float o2 = acc[i][2] * inv, o3 = acc[i][3] * inv;

        __nv_bfloat16 h0 = __float2bfloat16(o0);
        __nv_bfloat16 h1 = __float2bfloat16(o1);
        __nv_bfloat16 h2 = __float2bfloat16(o2);
        __nv_bfloat16 h3 = __float2bfloat16(o3);
        uint2 hv, lv;
        hv.x = pack_bf16x2(o0, o1);       // equals (h0,h1) bit pattern
        hv.y = pack_bf16x2(o2, o3);
        lv.x = pack_bf16x2(o0 - __bfloat162float(h0), o1 - __bfloat162float(h1));
        lv.y = pack_bf16x2(o2 - __bfloat162float(h2), o3 - __bfloat162float(h3));

        int arow = b * SS + q0 + 4 * ty + i;          // activation row
        int col = h * DHH + 4 * tx;                   // column within DD
        size_t base = (size_t)arow * K3 + col;
        *(uint2*)(g_a2 + base)        = hv;           // hi
        *(uint2*)(g_a2 + base + 1024) = lv;           // lo
        *(uint2*)(g_a2 + base + 2048) = hv;           // hi (dup)
    }
}

// ---------------------------------------------------------------------------
extern "C" void kernel_launch(void* const* d_in, const int* in_sizes, int n_in,
                              void* d_out, int out_size)
{
    (void)in_sizes; (void)n_in; (void)out_size;
    const float* query = (const float*)d_in[0];
    const float* key   = (const float*)d_in[1];
    const float* value = (const float*)d_in[2];
    const float* Wq = (const float*)d_in[3];
    const float* bq = (const float*)d_in[4];
    const float* Wk = (const float*)d_in[5];
    const float* bk = (const float*)d_in[6];
    const float* Wv = (const float*)d_in[7];
    const float* bv = (const float*)d_in[8];
    const float* Wo = (const float*)d_in[9];
    const float* bo = (const float*)d_in[10];
    float* out = (float*)d_out;

    float *qp, *kp, *vp;
    __nv_bfloat16 *a2, *w2;
    cudaGetSymbolAddress((void**)&qp, g_q);
    cudaGetSymbolAddress((void**)&kp, g_k);
    cudaGetSymbolAddress((void**)&vp, g_v);
    cudaGetSymbolAddress((void**)&a2, g_a2);
    cudaGetSymbolAddress((void**)&w2, g_w2);

    const int SMEM_GEMM = 4 * 16384;   // 4 stages x (A 8KB + B 8KB)
    cudaFuncSetAttribute(gemm_mma_kernel,
                         cudaFuncAttributeMaxDynamicSharedMemorySize, SMEM_GEMM);
    cudaFuncSetAttribute(attn_window_kernel,
                         cudaFuncAttributeMaxDynamicSharedMemorySize, ATT_SMEM);

    dim3 gblk(256);
    dim3 ggrd(DD / 128, MM / 128);     // (8, 32)
    const int SPA_GRID = MM;
    const int SPW_GRID = DD;

    // Q = query @ Wq^T + bq
    split_kernel<1><<<SPA_GRID, 256>>>(query, a2, MM);
    split_kernel<0><<<SPW_GRID, 256>>>(Wq, w2, DD);
    gemm_mma_kernel<<<ggrd, gblk, SMEM_GEMM>>>(a2, w2, bq, qp);
    // K
    split_kernel<1><<<SPA_GRID, 256>>>(key, a2, MM);
    split_kernel<0><<<SPW_GRID, 256>>>(Wk, w2, DD);
    gemm_mma_kernel<<<ggrd, gblk, SMEM_GEMM>>>(a2, w2, bk, kp);
    // V
    split_kernel<1><<<SPA_GRID, 256>>>(value, a2, MM);
    split_kernel<0><<<SPW_GRID, 256>>>(Wv, w2, DD);
    gemm_mma_kernel<<<ggrd, gblk, SMEM_GEMM>>>(a2, w2, bv, vp);

    // attention writes split bf16 activations for the O-projection directly
    attn_window_kernel<<<dim3(SS / 64, BB * HH), gblk, ATT_SMEM>>>();

    // out = attn @ Wo^T + bo
    split_kernel<0><<<SPW_GRID, 256>>>(Wo, w2, DD);
    gemm_mma_kernel<<<ggrd, gblk, SMEM_GEMM>>>(a2, w2, bo, out);
}

// round 11
// speedup vs baseline: 2.2106x; 1.2226x over previous
#include <cuda_runtime.h>
#include <cuda_bf16.h>
#include <cstdint>
#include <cstddef>

#define BB 2
#define SS 2048
#define DD 1024
#define HH 16
#define DHH 64
#define WINDOW 256
#define MM (BB * SS)        // 4096 activation rows
#define K3 3072             // 3-way split K
#define NST 96              // K3 / 32 pipeline stages

// ---------------- scratch (__device__ globals; no allocs allowed) ----------
__device__ __nv_bfloat16 g_qh[(size_t)MM * DD];   // projected Q hi (pre-scaled 0.125)
__device__ __nv_bfloat16 g_ql[(size_t)MM * DD];   // Q lo
__device__ __nv_bfloat16 g_kh[(size_t)MM * DD];
__device__ __nv_bfloat16 g_kl[(size_t)MM * DD];
__device__ __nv_bfloat16 g_vh[(size_t)MM * DD];
__device__ __nv_bfloat16 g_vl[(size_t)MM * DD];
__device__ __nv_bfloat16 g_a2[(size_t)MM * K3];   // split activations (GEMM A)
__device__ __nv_bfloat16 g_w2[(size_t)DD * K3];   // split weights

// ---------------- PTX helpers ----------------------------------------------
__device__ __forceinline__ uint32_t smem_u32(const void* p) {
    uint32_t a;
    asm("{ .reg .u64 t; cvta.to.shared.u64 t, %1; cvt.u32.u64 %0, t; }"
        : "=r"(a) : "l"(p));
    return a;
}
__device__ __forceinline__ void cp_async16(uint32_t saddr, const void* gaddr) {
    asm volatile("cp.async.cg.shared.global [%0], [%1], 16;"
                 :: "r"(saddr), "l"(gaddr));
}
#define CP_COMMIT() asm volatile("cp.async.commit_group;" ::: "memory")
#define CP_WAIT2()  asm volatile("cp.async.wait_group 2;" ::: "memory")
#define CP_WAIT0()  asm volatile("cp.async.wait_group 0;" ::: "memory")

__device__ __forceinline__ void ldmatrix_x4(uint32_t* r, uint32_t addr) {
    asm volatile("ldmatrix.sync.aligned.m8n8.x4.shared.b16 {%0,%1,%2,%3}, [%4];"
                 : "=r"(r[0]), "=r"(r[1]), "=r"(r[2]), "=r"(r[3]) : "r"(addr));
}
__device__ __forceinline__ void ldmatrix_x4_trans(uint32_t* r, uint32_t addr) {
    asm volatile("ldmatrix.sync.aligned.m8n8.x4.trans.shared.b16 {%0,%1,%2,%3}, [%4];"
                 : "=r"(r[0]), "=r"(r[1]), "=r"(r[2]), "=r"(r[3]) : "r"(addr));
}
__device__ __forceinline__ void mma_bf16(float* d, const uint32_t* a,
                                         uint32_t b0, uint32_t b1) {
    asm volatile(
        "mma.sync.aligned.m16n8k16.row.col.f32.bf16.bf16.f32 "
        "{%0,%1,%2,%3}, {%4,%5,%6,%7}, {%8,%9}, {%0,%1,%2,%3};"
        : "+f"(d[0]), "+f"(d[1]), "+f"(d[2]), "+f"(d[3])
        : "r"(a[0]), "r"(a[1]), "r"(a[2]), "r"(a[3]), "r"(b0), "r"(b1));
}
__device__ __forceinline__ uint32_t pack_bf16x2(float a, float b) {
    __nv_bfloat162 t;
    t.x = __float2bfloat16(a);
    t.y = __float2bfloat16(b);
    return *(uint32_t*)&t;
}
// hi = bf16x2(a,b); lo = bf16x2(residuals)
__device__ __forceinline__ uint32_t pack_hi_lo(float a, float b, uint32_t& lo) {
    __nv_bfloat16 ha = __float2bfloat16(a), hb = __float2bfloat16(b);
    lo = pack_bf16x2(a - __bfloat162float(ha), b - __bfloat162float(hb));
    __nv_bfloat162 t; t.x = ha; t.y = hb;
    return *(uint32_t*)&t;
}

// ---------------------------------------------------------------------------
// fp32 -> bf16 3-way split. AMODE=1: [hi|lo|hi] (activations)
//                           AMODE=0: [hi|hi|lo] (weights)
// ---------------------------------------------------------------------------
template <int AMODE>
__global__ void split_kernel(const float* __restrict__ in,
                             __nv_bfloat16* __restrict__ out, int rows)
{
    int i4 = blockIdx.x * blockDim.x + threadIdx.x;
    if (i4 >= rows * (DD / 4)) return;
    int row = i4 >> 8;
    int c4 = i4 & 255;
    float4 f = ((const float4*)in)[i4];

    uint32_t lA, lB;
    uint32_t hA = pack_hi_lo(f.x, f.y, lA);
    uint32_t hB = pack_hi_lo(f.z, f.w, lB);

    size_t base = (size_t)row * K3 + c4 * 4;
    uint32_t* o0 = (uint32_t*)(out + base);
    uint32_t* o1 = (uint32_t*)(out + base + 1024);
    uint32_t* o2 = (uint32_t*)(out + base + 2048);
    o0[0] = hA; o0[1] = hB;
    if (AMODE) { o1[0] = lA; o1[1] = lB; o2[0] = hA; o2[1] = hB; }
    else       { o1[0] = hA; o1[1] = hB; o2[0] = lA; o2[1] = lB; }
}

// ---------------------------------------------------------------------------
// mma.sync bf16 GEMM: C = A2[M,K3] @ W2[DD,K3]^T + bias, then
//   OSPLIT=0: fp32 store to C
//   OSPLIT=1: (v*oscale) -> bf16 hi/lo stores to Chi/Clo  (for attention)
// ---------------------------------------------------------------------------
template <int OSPLIT>
__global__ __launch_bounds__(256, 2)
void gemm_mma_kernel(const __nv_bfloat16* __restrict__ A2,
                     const __nv_bfloat16* __restrict__ W2,
                     const float* __restrict__ bias,
                     float* __restrict__ C,
                     __nv_bfloat16* __restrict__ Chi,
                     __nv_bfloat16* __restrict__ Clo,
                     float oscale)
{
    extern __shared__ char smem_raw[];
    const uint32_t smem = smem_u32(smem_raw);

    const int tid  = threadIdx.x;
    const int wid  = tid >> 5;
    const int lane = tid & 31;
    const int wm = wid & 1;
    const int wn = wid >> 1;
    const int n0 = blockIdx.x * 128;
    const int m0 = blockIdx.y * 128;

    const __nv_bfloat16* Abase = A2 + (size_t)m0 * K3;
    const __nv_bfloat16* Wbase = W2 + (size_t)n0 * K3;

    const int cl0 = tid;
    const int cl1 = tid + 256;
    const int lr0 = cl0 >> 2, lc0 = cl0 & 3;
    const int lr1 = cl1 >> 2, lc1 = cl1 & 3;
    const uint32_t so0 = lr0 * 64 + ((lc0 ^ ((lr0 >> 1) & 3)) << 4);
    const uint32_t so1 = lr1 * 64 + ((lc1 ^ ((lr1 >> 1) & 3)) << 4);

    const int lane15 = lane & 15;
    const int hib = lane >> 4;
    uint32_t a_off[4], b_off[2];
    int a_sw[4], b_sw[2];
#pragma unroll
    for (int mt = 0; mt < 4; mt++) {
        int r = wm * 64 + mt * 16 + lane15;
        a_off[mt] = r * 64;
        a_sw[mt] = (r >> 1) & 3;
    }
#pragma unroll
    for (int bp = 0; bp < 2; bp++) {
        int r = wn * 32 + bp * 16 + lane15;
        b_off[bp] = 8192 + r * 64;
        b_sw[bp] = (r >> 1) & 3;
    }

    float d[4][4][4];
#pragma unroll
    for (int mt = 0; mt < 4; mt++)
#pragma unroll
        for (int nt = 0; nt < 4; nt++)
#pragma unroll
            for (int j = 0; j < 4; j++) d[mt][nt][j] = 0.f;

#pragma unroll
    for (int st = 0; st < 3; st++) {
        uint32_t sb = smem + (st & 3) * 16384;
        const __nv_bfloat16* Ag = Abase + st * 32;
        const __nv_bfloat16* Wg = Wbase + st * 32;
        cp_async16(sb + so0,        Ag + (size_t)lr0 * K3 + lc0 * 8);
        cp_async16(sb + 8192 + so0, Wg + (size_t)lr0 * K3 + lc0 * 8);
        cp_async16(sb + so1,        Ag + (size_t)lr1 * K3 + lc1 * 8);
        cp_async16(sb + 8192 + so1, Wg + (size_t)lr1 * K3 + lc1 * 8);
        CP_COMMIT();
    }

    for (int st = 0; st < NST; st++) {
        CP_WAIT2();
        __syncthreads();

        int pf = st + 3;
        if (pf < NST) {
            uint32_t sb = smem + (pf & 3) * 16384;
            const __nv_bfloat16* Ag = Abase + pf * 32;
            const __nv_bfloat16* Wg = Wbase + pf * 32;
            cp_async16(sb + so0,        Ag + (size_t)lr0 * K3 + lc0 * 8);
            cp_async16(sb + 8192 + so0, Wg + (size_t)lr0 * K3 + lc0 * 8);
            cp_async16(sb + so1,        Ag + (size_t)lr1 * K3 + lc1 * 8);
            cp_async16(sb + 8192 + so1, Wg + (size_t)lr1 * K3 + lc1 * 8);
        }
        CP_COMMIT();

        uint32_t base = smem + (st & 3) * 16384;
#pragma unroll
        for (int s16 = 0; s16 < 2; s16++) {
            int ch = s16 * 2 + hib;
            uint32_t a[4][4], bb[2][4];
#pragma unroll
            for (int mt = 0; mt < 4; mt++)
                ldmatrix_x4(a[mt], base + a_off[mt] + ((ch ^ a_sw[mt]) << 4));
#pragma unroll
            for (int bp = 0; bp < 2; bp++)
                ldmatrix_x4(bb[bp], base + b_off[bp] + ((ch ^ b_sw[bp]) << 4));
#pragma unroll
            for (int mt = 0; mt < 4; mt++)
#pragma unroll
                for (int nt = 0; nt < 4; nt++)
                    mma_bf16(d[mt][nt], a[mt],
                             bb[nt >> 1][nt & 1],
                             bb[nt >> 1][(nt & 1) + 2]);
        }
    }

    const int ncol0 = n0 + wn * 32 + (lane & 3) * 2;
    const int mrow0 = m0 + wm * 64 + (lane >> 2);
#pragma unroll
    for (int nt = 0; nt < 4; nt++) {
        float2 bv = *(const float2*)(bias + ncol0 + nt * 8);
#pragma unroll
        for (int mt = 0; mt < 4; mt++) {
            int r1 = mrow0 + mt * 16;
            float v0 = (d[mt][nt][0] + bv.x) * oscale;
            float v1 = (d[mt][nt][1] + bv.y) * oscale;
            float v2 = (d[mt][nt][2] + bv.x) * oscale;
            float v3 = (d[mt][nt][3] + bv.y) * oscale;
            if (OSPLIT) {
                uint32_t lo0, lo1;
                uint32_t hi0 = pack_hi_lo(v0, v1, lo0);
                uint32_t hi1 = pack_hi_lo(v2, v3, lo1);
                size_t p0 = (size_t)r1 * DD + ncol0 + nt * 8;
                size_t p1 = (size_t)(r1 + 8) * DD + ncol0 + nt * 8;
                *(uint32_t*)(Chi + p0) = hi0;
                *(uint32_t*)(Clo + p0) = lo0;
                *(uint32_t*)(Chi + p1) = hi1;
                *(uint32_t*)(Clo + p1) = lo1;
            } else {
                *(float2*)(C + (size_t)r1 * DD + ncol0 + nt * 8) =
                    make_float2(v0, v1);
                *(float2*)(C + (size_t)(r1 + 8) * DD + ncol0 + nt * 8) =
                    make_float2(v2, v3);
            }
        }
    }
}

// ---------------------------------------------------------------------------
// Tensor-core windowed flash attention.
// Block: 128 thr / 4 warps; 64-query tile per block; 64-key phases (5).
// Warp w owns rows 16w..16w+15 x all 64 keys / 64 dh output.
// QK^T: 3-term bf16 split (Qhi*Khi + Qlo*Khi + Qhi*Klo); Q pre-scaled 0.125.
// PV:   3-term (Phi*Vhi + Plo*Vhi + Phi*Vlo); P fragments packed from accums.
// smem tiles 64x64 bf16 (128B rows), chunk swizzle ch ^ (row&7).
// Epilogue writes g_a2 [hi|lo|hi] for the O-projection GEMM.
// ---------------------------------------------------------------------------
#define ATT_SMEM (6 * 8192)   // Qh Ql Kh Kl Vh Vl

__global__ __launch_bounds__(128, 3)
void attn_tc_kernel()
{
    extern __shared__ __nv_bfloat16 smb[];
    const uint32_t sQh = smem_u32(smb);
    const uint32_t sQl = sQh + 8192;
    const uint32_t sKh = sQh + 16384;
    const uint32_t sKl = sQh + 24576;
    const uint32_t sVh = sQh + 32768;
    const uint32_t sVl = sQh + 40960;

    const int tid = threadIdx.x;
    const int w = tid >> 5;
    const int lane = tid & 31;
    const int lane15 = lane & 15;
    const int hib = lane >> 4;
    const int qt = blockIdx.x;
    const int bh = blockIdx.y;
    const int b = bh >> 4;
    const int h = bh & 15;
    const int q0 = qt * 64;

    const size_t gbase = (size_t)(b * SS) * DD + h * DHH;

    // ---- load Q hi/lo tiles (64x64 bf16 each), swizzled ----
#pragma unroll
    for (int t = 0; t < 4; t++) {
        int q = tid + t * 128;            // chunk 0..511
        int row = q >> 3, ch = q & 7;
        uint32_t off = row * 128 + ((ch ^ (row & 7)) << 4);
        const __nv_bfloat16* src = g_qh + gbase + (size_t)(q0 + row) * DD + ch * 8;
        cp_async16(sQh + off, src);
        cp_async16(sQl + off, g_ql + gbase + (size_t)(q0 + row) * DD + ch * 8);
    }
    CP_COMMIT();
    CP_WAIT0();
    __syncthreads();

    // ---- Q fragments (held all phases): 4 k16 chunks ----
    uint32_t qh[4][4], ql[4][4];
    {
        int ar = w * 16 + lane15;
#pragma unroll
        for (int kc = 0; kc < 4; kc++) {
            uint32_t off = ar * 128 + (((kc * 2 + hib) ^ (ar & 7)) << 4);
            ldmatrix_x4(qh[kc], sQh + off);
            ldmatrix_x4(ql[kc], sQl + off);
        }
    }

    const int r0 = q0 + w * 16 + (lane >> 2);   // global query rows
    const int r1 = r0 + 8;

    float o[8][4];
#pragma unroll
    for (int j = 0; j < 8; j++)
#pragma unroll
        for (int x = 0; x < 4; x++) o[j][x] = 0.f;
    float m0r = -1e30f, m1r = -1e30f, l0r = 0.f, l1r = 0.f;

    for (int kb = 0; kb < 5; kb++) {
        int kstart = q0 - 256 + kb * 64;
        if (kstart < 0) continue;         // uniform across block

        __syncthreads();                  // prior-phase K/V reads done
        // ---- load K/V hi/lo tiles ----
#pragma unroll
        for (int t = 0; t < 4; t++) {
            int q = tid + t * 128;
            int row = q >> 3, ch = q & 7;
            uint32_t off = row * 128 + ((ch ^ (row & 7)) << 4);
            size_t gs = gbase + (size_t)(kstart + row) * DD + ch * 8;
            cp_async16(sKh + off, g_kh + gs);
            cp_async16(sKl + off, g_kl + gs);
            cp_async16(sVh + off, g_vh + gs);
            cp_async16(sVl + off, g_vl + gs);
        }
        CP_COMMIT();
        CP_WAIT0();
        __syncthreads();

        // ---- S = Q @ K^T (3-term) ----
        float s[8][4];
#pragma unroll
        for (int j = 0; j < 8; j++)
#pragma unroll
            for (int x = 0; x < 4; x++) s[j][x] = 0.f;

#pragma unroll
        for (int kc = 0; kc < 4; kc++) {
            uint32_t kh[4][4], kl[4][4];
#pragma unroll
            for (int ng = 0; ng < 4; ng++) {
                int br = ng * 16 + lane15;
                uint32_t off = br * 128 + (((kc * 2 + hib) ^ (br & 7)) << 4);
                ldmatrix_x4(kh[ng], sKh + off);
                ldmatrix_x4(kl[ng], sKl + off);
            }
#pragma unroll
            for (int j = 0; j < 8; j++) {
                // non-trans B pairing: (r[j&1], r[(j&1)+2])
                uint32_t b0h = kh[j >> 1][j & 1], b1h = kh[j >> 1][(j & 1) + 2];
                uint32_t b0l = kl[j >> 1][j & 1], b1l = kl[j >> 1][(j & 1) + 2];
                mma_bf16(s[j], qh[kc], b0h, b1h);
                mma_bf16(s[j], ql[kc], b0h, b1h);
                mma_bf16(s[j], qh[kc], b0l, b1l);
            }
        }

        // ---- mask + online softmax ----
        const int cb = kstart + 2 * (lane & 3);
#pragma unroll
        for (int j = 0; j < 8; j++) {
            int c0 = cb + 8 * j, c1 = c0 + 1;
            if (!(c0 <= r0 && c0 >= r0 - (WINDOW - 1))) s[j][0] = -1e4f;
            if (!(c1 <= r0 && c1 >= r0 - (WINDOW - 1))) s[j][1] = -1e4f;
            if (!(c0 <= r1 && c0 >= r1 - (WINDOW - 1))) s[j][2] = -1e4f;
            if (!(c1 <= r1 && c1 >= r1 - (WINDOW - 1))) s[j][3] = -1e4f;
        }
        float ml0 = -1e30f, ml1 = -1e30f;
#pragma unroll
        for (int j = 0; j < 8; j++) {
            ml0 = fmaxf(ml0, fmaxf(s[j][0], s[j][1]));
            ml1 = fmaxf(ml1, fmaxf(s[j][2], s[j][3]));
        }
        ml0 = fmaxf(ml0, __shfl_xor_sync(0xffffffffu, ml0, 1));
        ml0 = fmaxf(ml0, __shfl_xor_sync(0xffffffffu, ml0, 2));
        ml1 = fmaxf(ml1, __shfl_xor_sync(0xffffffffu, ml1, 1));
        ml1 = fmaxf(ml1, __shfl_xor_sync(0xffffffffu, ml1, 2));
        float mn0 = fmaxf(m0r, ml0), mn1 = fmaxf(m1r, ml1);
        float fac0 = __expf(m0r - mn0), fac1 = __expf(m1r - mn1);
        float ps0 = 0.f, ps1 = 0.f;
#pragma unroll
        for (int j = 0; j < 8; j++) {
            // masked entries (-1e4) underflow to exactly 0 (mn >= real max)
            s[j][0] = __expf(s[j][0] - mn0);
            s[j][1] = __expf(s[j][1] - mn0);
            s[j][2] = __expf(s[j][2] - mn1);
            s[j][3] = __expf(s[j][3] - mn1);
            ps0 += s[j][0] + s[j][1];
            ps1 += s[j][2] + s[j][3];
        }
        ps0 += __shfl_xor_sync(0xffffffffu, ps0, 1);
        ps0 += __shfl_xor_sync(0xffffffffu, ps0, 2);
        ps1 += __shfl_xor_sync(0xffffffffu, ps1, 1);
        ps1 += __shfl_xor_sync(0xffffffffu, ps1, 2);
        l0r = l0r * fac0 + ps0;  m0r = mn0;
        l1r = l1r * fac1 + ps1;  m1r = mn1;
#pragma unroll
        for (int j = 0; j < 8; j++) {
            o[j][0] *= fac0; o[j][1] *= fac0;
            o[j][2] *= fac1; o[j][3] *= fac1;
        }

        // ---- pack P fragments (C-frag -> A-frag identity) ----
        uint32_t phi[4][4], plo[4][4];
#pragma unroll
        for (int kc = 0; kc < 4; kc++) {
            phi[kc][0] = pack_hi_lo(s[2 * kc][0],     s[2 * kc][1],     plo[kc][0]);
            phi[kc][1] = pack_hi_lo(s[2 * kc][2],     s[2 * kc][3],     plo[kc][1]);
            phi[kc][2] = pack_hi_lo(s[2 * kc + 1][0], s[2 * kc + 1][1], plo[kc][2]);
            phi[kc][3] = pack_hi_lo(s[2 * kc + 1][2], s[2 * kc + 1][3], plo[kc][3]);
        }

        // ---- O += P @ V (3-term), V via ldmatrix.trans ----
#pragma unroll
        for (int kc = 0; kc < 4; kc++) {
            uint32_t vh[4][4], vl[4][4];
            int vr = kc * 16 + lane15;        // key row
#pragma unroll
            for (int ng = 0; ng < 4; ng++) {
                uint32_t off = vr * 128 + (((ng * 2 + hib) ^ (vr & 7)) << 4);
                ldmatrix_x4_trans(vh[ng], sVh + off);
                ldmatrix_x4_trans(vl[ng], sVl + off);
            }
#pragma unroll
            for (int j = 0; j < 8; j++) {
                // TRANS B pairing: (r[(j&1)*2], r[(j&1)*2+1]) — transpose
                // swaps k-half vs n-block roles relative to non-trans.
                uint32_t b0h = vh[j >> 1][(j & 1) * 2];
                uint32_t b1h = vh[j >> 1][(j & 1) * 2 + 1];
                uint32_t b0l = vl[j >> 1][(j & 1) * 2];
                uint32_t b1l = vl[j >> 1][(j & 1) * 2 + 1];
                mma_bf16(o[j], phi[kc], b0h, b1h);
                mma_bf16(o[j], plo[kc], b0h, b1h);
                mma_bf16(o[j], phi[kc], b0l, b1l);
            }
        }
    }

    // ---- epilogue: /l, split-write g_a2 [hi|lo|hi] ----
    float inv0 = 1.f / l0r, inv1 = 1.f / l1r;
    const int colbase = h * DHH + 2 * (lane & 3);
#pragma unroll
    for (int j = 0; j < 8; j++) {
        int col = colbase + 8 * j;
        float a0 = o[j][0] * inv0, a1 = o[j][1] * inv0;
        float a2 = o[j][2] * inv1, a3 = o[j][3] * inv1;
        uint32_t lo0, lo1;
        uint32_t hi0 = pack_hi_lo(a0, a1, lo0);
        uint32_t hi1 = pack_hi_lo(a2, a3, lo1);
        size_t base0 = (size_t)(b * SS + r0) * K3 + col;
        size_t base1 = (size_t)(b * SS + r1) * K3 + col;
        *(uint32_t*)(g_a2 + base0)        = hi0;
        *(uint32_t*)(g_a2 + base0 + 1024) = lo0;
        *(uint32_t*)(g_a2 + base0 + 2048) = hi0;
        *(uint32_t*)(g_a2 + base1)        = hi1;
        *(uint32_t*)(g_a2 + base1 + 1024) = lo1;
        *(uint32_t*)(g_a2 + base1 + 2048) = hi1;
    }
}

// ---------------------------------------------------------------------------
extern "C" void kernel_launch(void* const* d_in, const int* in_sizes, int n_in,
                              void* d_out, int out_size)
{
    (void)in_sizes; (void)n_in; (void)out_size;
    const float* query = (const float*)d_in[0];
    const float* key   = (const float*)d_in[1];
    const float* value = (const float*)d_in[2];
    const float* Wq = (const float*)d_in[3];
    const float* bq = (const float*)d_in[4];
    const float* Wk = (const float*)d_in[5];
    const float* bk = (const float*)d_in[6];
    const float* Wv = (const float*)d_in[7];
    const float* bv = (const float*)d_in[8];
    const float* Wo = (const float*)d_in[9];
    const float* bo = (const float*)d_in[10];
    float* out = (float*)d_out;

    __nv_bfloat16 *a2, *w2, *qh, *ql, *kh, *kl, *vh, *vl;
    cudaGetSymbolAddress((void**)&a2, g_a2);
    cudaGetSymbolAddress((void**)&w2, g_w2);
    cudaGetSymbolAddress((void**)&qh, g_qh);
    cudaGetSymbolAddress((void**)&ql, g_ql);
    cudaGetSymbolAddress((void**)&kh, g_kh);
    cudaGetSymbolAddress((void**)&kl, g_kl);
    cudaGetSymbolAddress((void**)&vh, g_vh);
    cudaGetSymbolAddress((void**)&vl, g_vl);

    const int SMEM_GEMM = 4 * 16384;
    cudaFuncSetAttribute(gemm_mma_kernel<0>,
                         cudaFuncAttributeMaxDynamicSharedMemorySize, SMEM_GEMM);
    cudaFuncSetAttribute(gemm_mma_kernel<1>,
                         cudaFuncAttributeMaxDynamicSharedMemorySize, SMEM_GEMM);
    cudaFuncSetAttribute(attn_tc_kernel,
                         cudaFuncAttributeMaxDynamicSharedMemorySize, ATT_SMEM);

    dim3 gblk(256);
    dim3 ggrd(DD / 128, MM / 128);
    const int SPA_GRID = MM;
    const int SPW_GRID = DD;

    // Q = (query @ Wq^T + bq) * 0.125  -> split bf16
    split_kernel<1><<<SPA_GRID, 256>>>(query, a2, MM);
    split_kernel<0><<<SPW_GRID, 256>>>(Wq, w2, DD);
    gemm_mma_kernel<1><<<ggrd, gblk, SMEM_GEMM>>>(a2, w2, bq, nullptr, qh, ql, 0.125f);
    // K
    split_kernel<1><<<SPA_GRID, 256>>>(key, a2, MM);
    split_kernel<0><<<SPW_GRID, 256>>>(Wk, w2, DD);
    gemm_mma_kernel<1><<<ggrd, gblk, SMEM_GEMM>>>(a2, w2, bk, nullptr, kh, kl, 1.0f);
    // V
    split_kernel<1><<<SPA_GRID, 256>>>(value, a2, MM);
    split_kernel<0><<<SPW_GRID, 256>>>(Wv, w2, DD);
    gemm_mma_kernel<1><<<ggrd, gblk, SMEM_GEMM>>>(a2, w2, bv, nullptr, vh, vl, 1.0f);

    // tensor-core attention: writes split activations into g_a2
    attn_tc_kernel<<<dim3(SS / 64, BB * HH), 128, ATT_SMEM>>>();

    // out = attn @ Wo^T + bo
    split_kernel<0><<<SPW_GRID, 256>>>(Wo, w2, DD);
    gemm_mma_kernel<0><<<ggrd, gblk, SMEM_GEMM>>>(a2, w2, bo, out, nullptr, nullptr, 1.0f);
}